// round 1
// baseline (speedup 1.0000x reference)
#include <cuda_runtime.h>
#include <cstdint>

#define N_NODES 200000
#define DIM 64
#define NQ 4096
#define GRP 64
#define E1N 262144
#define E0N 131072
#define KSEL 10

// Output layout (f32 concat): score[N], repr[N*64], pruned_edges[Q*K*8], orig_idx[Q*K]
#define OFF_REPR  (N_NODES)
#define OFF_PE    (N_NODES + N_NODES*DIM)
#define OFF_OI    (OFF_PE + NQ*KSEL*8)

// ---------------- scratch (device globals; no allocation) ----------------
__device__ float    g_M [256*256];
__device__ float    g_MT[256*256];
__device__ float    g_B1[64*192];     // [k][0:128]=M[k,0:128] (M00|M01), [128+i]=M10^T[k,i]
__device__ float    g_B2[64*64];      // M11^T
__device__ float    g_BL[64*64];      // W_lin^T
__device__ float    g_Qd [NQ*DIM];
__device__ float    g_Qce[NQ*DIM];
__device__ float    g_Qv [NQ*DIM];
__device__ float    g_Qk0[NQ];
__device__ float    g_nodeT[(size_t)N_NODES*192];
__device__ float    g_Z  [(size_t)E1N*DIM];
__device__ float    g_logit[E1N];            // logits, then exp values (in place)
__device__ unsigned g_segmax[N_NODES];
__device__ float    g_segsum[N_NODES];
__device__ int      g_has[N_NODES];
__device__ float    g_H1[(size_t)N_NODES*DIM];
__device__ float    g_H2[(size_t)N_NODES*DIM];
__device__ int      g_psrc[NQ*KSEL];
__device__ int      g_pdst[NQ*KSEL];
__device__ float    g_ptrans[NQ*KSEL];

// ---------------- helpers ----------------
__device__ __forceinline__ unsigned encf(float f) {
    unsigned u = __float_as_uint(f);
    return (u & 0x80000000u) ? ~u : (u | 0x80000000u);
}
__device__ __forceinline__ float decf(unsigned u) {
    return (u & 0x80000000u) ? __uint_as_float(u & 0x7fffffffu) : __uint_as_float(~u);
}

// ---------------- init kernels ----------------
__global__ void k_init1(float* outScore) {
    int i = blockIdx.x * blockDim.x + threadIdx.x;
    if (i < N_NODES) { g_segmax[i] = 0u; g_segsum[i] = 0.f; g_has[i] = 0; outScore[i] = 0.f; }
}
__global__ void k_init2() {
    int i = blockIdx.x * blockDim.x + threadIdx.x;
    if (i < N_NODES) { g_segmax[i] = 0u; g_segsum[i] = 0.f; g_has[i] = 0; }
}

// M = Wq^T Wk  (and transposed copy)
__global__ void k_computeM(const float* __restrict__ Wq, const float* __restrict__ Wk) {
    int i = blockIdx.x, j = threadIdx.x;
    float acc = 0.f;
    for (int k = 0; k < 256; k++) acc = fmaf(Wq[k*256 + i], Wk[k*256 + j], acc);
    g_M[i*256 + j] = acc;
    g_MT[j*256 + i] = acc;
}

__global__ void k_buildB(const float* __restrict__ W_lin) {
    int t = blockIdx.x * blockDim.x + threadIdx.x;
    if (t < 64*192) {
        int k = t / 192, c = t % 192;
        float v;
        if (c < 128) v = g_M[k*256 + c];                 // M00|M01
        else         v = g_M[(64 + (c-128))*256 + k];    // M10^T[k,i] = M[64+i, k]
        g_B1[t] = v;
    } else if (t < 64*192 + 64*64) {
        int t2 = t - 64*192; int k = t2 / 64, i = t2 % 64;
        g_B2[t2] = g_M[(64+i)*256 + (64+k)];             // M11^T[k,i] = M[64+i,64+k]
    } else if (t < 64*192 + 2*64*64) {
        int t3 = t - 64*192 - 64*64; int k = t3 / 64, i = t3 % 64;
        g_BL[t3] = W_lin[i*64 + k];                      // W_lin^T
    }
}

// per-query tables: d, ce, v (64 each) and scalar k0
__global__ void k_qtab(const float* __restrict__ qst, const float* __restrict__ qrl) {
    int q = blockIdx.x, i = threadIdx.x;
    __shared__ float ss[64], st[64];
    __shared__ float red[2];
    ss[i] = qst[q*64 + i]; st[i] = qrl[q*64 + i];
    __syncthreads();
    float d = 0.f, ce = 0.f, v = 0.f, A = 0.f, B = 0.f;
    for (int k = 0; k < 64; k++) {
        float sk = ss[k], tk = st[k];
        const float* Mr128  = g_M  + (128+k)*256;
        const float* Mr192  = g_M  + (192+k)*256;
        const float* MTr128 = g_MT + (128+k)*256;
        const float* MTr192 = g_MT + (192+k)*256;
        d  = fmaf(sk, Mr128[i], d);        d  = fmaf(tk, Mr192[i], d);
        ce = fmaf(sk, Mr128[64+i], ce);    ce = fmaf(tk, Mr192[64+i], ce);
        ce = fmaf(sk, MTr128[64+i], ce);   ce = fmaf(tk, MTr192[64+i], ce);
        v  = fmaf(sk, MTr128[i], v);       v  = fmaf(tk, MTr192[i], v);
        A  = fmaf(sk, MTr128[128+i], A);   A  = fmaf(tk, MTr192[128+i], A);
        B  = fmaf(sk, MTr128[192+i], B);   B  = fmaf(tk, MTr192[192+i], B);
    }
    g_Qd [q*64+i] = d;
    g_Qce[q*64+i] = ce;
    g_Qv [q*64+i] = v;
    float p = ss[i]*A + st[i]*B;
    for (int o = 16; o; o >>= 1) p += __shfl_xor_sync(~0u, p, o);
    if ((i & 31) == 0) red[i >> 5] = p;
    __syncthreads();
    if (i == 0) g_Qk0[q] = red[0] + red[1];
}

// generic C[rows x ncols] = A[rows x 64] @ B[64 x ncols]; rows % 64 == 0, ncols % 64 == 0
__global__ void k_gemm(const float* __restrict__ A, const float* __restrict__ B,
                       float* __restrict__ C, int ncols, int withEpi,
                       const float* __restrict__ bias) {
    __shared__ float sAT[64][72];
    __shared__ float sB[64][72];
    int t = threadIdx.x;
    int rb = blockIdx.x * 64, cb = blockIdx.y * 64;
    int r = t >> 4, c4 = (t & 15) * 4;
    for (int rr = r; rr < 64; rr += 16) {
        float4 av = *(const float4*)(A + (size_t)(rb + rr)*64 + c4);
        sAT[c4+0][rr] = av.x; sAT[c4+1][rr] = av.y; sAT[c4+2][rr] = av.z; sAT[c4+3][rr] = av.w;
    }
    for (int kk = r; kk < 64; kk += 16) {
        float4 bv = *(const float4*)(B + (size_t)kk*ncols + cb + c4);
        *(float4*)&sB[kk][c4] = bv;
    }
    __syncthreads();
    int tx = t & 15, ty = t >> 4;
    int r0 = ty * 4, c0 = tx * 4;
    float acc[4][4] = {};
    #pragma unroll
    for (int k = 0; k < 64; k++) {
        float4 av = *(const float4*)&sAT[k][r0];
        float4 bv = *(const float4*)&sB[k][c0];
        float a[4] = {av.x, av.y, av.z, av.w};
        float b[4] = {bv.x, bv.y, bv.z, bv.w};
        #pragma unroll
        for (int ii = 0; ii < 4; ii++)
            #pragma unroll
            for (int jj = 0; jj < 4; jj++)
                acc[ii][jj] = fmaf(a[ii], b[jj], acc[ii][jj]);
    }
    for (int ii = 0; ii < 4; ii++) {
        float4 o = make_float4(acc[ii][0], acc[ii][1], acc[ii][2], acc[ii][3]);
        if (withEpi) {
            o.x += bias[cb + c0 + 0]; o.y += bias[cb + c0 + 1];
            o.z += bias[cb + c0 + 2]; o.w += bias[cb + c0 + 3];
            o.x = o.x >= 0.f ? o.x : 0.01f * o.x;
            o.y = o.y >= 0.f ? o.y : 0.01f * o.y;
            o.z = o.z >= 0.f ? o.z : 0.01f * o.z;
            o.w = o.w >= 0.f ? o.w : 0.01f * o.w;
        }
        *(float4*)(C + (size_t)(rb + r0 + ii)*ncols + cb + c0) = o;
    }
}

// logits per edge (one warp/edge) + atomicMax into segment max
__global__ void k_logits(const int* __restrict__ edges, const float* __restrict__ rel,
                         const float* __restrict__ H, const float* __restrict__ prior,
                         const float* __restrict__ gammaPtr, int nE) {
    int w = (blockIdx.x * blockDim.x + threadIdx.x) >> 5;
    int lane = threadIdx.x & 31;
    if (w >= nE) return;
    int q = edges[w*8 + 0], src = edges[w*8 + 6], dst = edges[w*8 + 7];
    const float2* hs  = (const float2*)(H + (size_t)src*64);
    const float2* hd  = (const float2*)(H + (size_t)dst*64);
    const float2* nts = (const float2*)(g_nodeT + (size_t)src*192);
    const float2* ntd = (const float2*)(g_nodeT + (size_t)dst*192);
    const float2* rp  = (const float2*)(rel + (size_t)w*64);
    const float2* zp  = (const float2*)(g_Z + (size_t)w*64);
    const float2* qd  = (const float2*)(g_Qd  + (size_t)q*64);
    const float2* qc  = (const float2*)(g_Qce + (size_t)q*64);
    const float2* qv  = (const float2*)(g_Qv  + (size_t)q*64);
    float2 P  = nts[lane];
    float2 U  = nts[32 + lane];
    float2 Wd = ntd[64 + lane];
    float2 hdv = hd[lane], hsv = hs[lane], rv = rp[lane], zv = zp[lane];
    float2 dq = qd[lane], cq = qc[lane], vq = qv[lane];
    float acc = (P.x + dq.x) * hdv.x + (P.y + dq.y) * hdv.y;
    acc = fmaf(rv.x, (U.x + zv.x + cq.x + Wd.x), acc);
    acc = fmaf(rv.y, (U.y + zv.y + cq.y + Wd.y), acc);
    acc = fmaf(vq.x, hsv.x, acc);
    acc = fmaf(vq.y, hsv.y, acc);
    for (int o = 16; o; o >>= 1) acc += __shfl_xor_sync(~0u, acc, o);
    if (lane == 0) {
        float l = acc + g_Qk0[q];
        if (prior) l = fmaf(gammaPtr[0], prior[w], l);
        g_logit[w] = l;
        atomicMax(&g_segmax[src], encf(l));
    }
}

// exp(l - max) + segment sum; optional "has src" marking (stage 0)
__global__ void k_pass2(const int* __restrict__ edges, int markHas, int nE) {
    int e = blockIdx.x * blockDim.x + threadIdx.x;
    if (e >= nE) return;
    int src = edges[e*8 + 6];
    float mx = decf(g_segmax[src]);
    float v = expf(g_logit[e] - mx);
    g_logit[e] = v;
    atomicAdd(&g_segsum[src], v);
    if (markHas) g_has[src] = 1;
}

// top-10 of 64 per query, write pruned outputs + node-score atomics + has flags
__global__ void k_topk(const int* __restrict__ edges1, const float* __restrict__ score,
                       float* __restrict__ out) {
    int w = (blockIdx.x * blockDim.x + threadIdx.x) >> 5;
    int lane = threadIdx.x & 31;
    if (w >= NQ) return;
    int g0 = lane, g1 = lane + 32;
    int e0 = w*64 + g0, e1 = w*64 + g1;
    int s0 = edges1[e0*8 + 6], s1 = edges1[e1*8 + 6];
    float tr0 = g_logit[e0] / g_segsum[s0];
    float tr1 = g_logit[e1] / g_segsum[s1];
    float v0 = tr0 * score[s0];
    float v1 = tr1 * score[s1];
    int myG = 0; float myTr = 0.f;
    for (int k = 0; k < KSEL; k++) {
        float bv; int bg; float bt;
        if (v0 >= v1) { bv = v0; bg = g0; bt = tr0; }
        else          { bv = v1; bg = g1; bt = tr1; }
        for (int o = 16; o; o >>= 1) {
            float ov = __shfl_xor_sync(~0u, bv, o);
            int   og = __shfl_xor_sync(~0u, bg, o);
            float ot = __shfl_xor_sync(~0u, bt, o);
            if (ov > bv || (ov == bv && og < bg)) { bv = ov; bg = og; bt = ot; }
        }
        if (lane == k) { myG = bg; myTr = bt; }
        if (g0 == bg) v0 = -__int_as_float(0x7f800000);
        if (g1 == bg) v1 = -__int_as_float(0x7f800000);
    }
    if (lane < KSEL) {
        int orig = w*64 + myG;
        int oi = w*KSEL + lane;
        int src = edges1[orig*8 + 6], dst = edges1[orig*8 + 7];
        g_psrc[oi] = src; g_pdst[oi] = dst; g_ptrans[oi] = myTr;
        g_has[src] = 1;
        atomicAdd(out + dst, myTr * score[src]);
        float* pe = out + OFF_PE + (size_t)oi*8;
        for (int c = 0; c < 8; c++) pe[c] = (float)edges1[orig*8 + c];
        out[OFF_OI + oi] = (float)orig;
    }
}

// Hdst[n] = has[n] ? 0 : Hsrc[n]
__global__ void k_Hinit(const float* __restrict__ Hsrc, float* __restrict__ Hdst) {
    int i = blockIdx.x * blockDim.x + threadIdx.x;
    if (i >= N_NODES * 16) return;
    int n = i >> 4;
    float4 v;
    if (g_has[n]) v = make_float4(0.f, 0.f, 0.f, 0.f);
    else          v = ((const float4*)Hsrc)[i];
    ((float4*)Hdst)[i] = v;
}

// pruned-edge scatter: H1[src] += trans * H[dst]
__global__ void k_scatter1(const float* __restrict__ H) {
    int w = (blockIdx.x * blockDim.x + threadIdx.x) >> 5;
    int lane = threadIdx.x & 31;
    if (w >= NQ*KSEL) return;
    int src = g_psrc[w], dst = g_pdst[w];
    float t = g_ptrans[w];
    float2 hv = ((const float2*)(H + (size_t)dst*64))[lane];
    atomicAdd(&g_H1[(size_t)src*64 + 2*lane + 0], t * hv.x);
    atomicAdd(&g_H1[(size_t)src*64 + 2*lane + 1], t * hv.y);
}

// edges0 scatter: H2[src] += trans0 * H1[dst]
__global__ void k_scatter0(const int* __restrict__ edges0) {
    int w = (blockIdx.x * blockDim.x + threadIdx.x) >> 5;
    int lane = threadIdx.x & 31;
    if (w >= E0N) return;
    int src = edges0[w*8 + 6], dst = edges0[w*8 + 7];
    float t = g_logit[w] / g_segsum[src];
    float2 hv = ((const float2*)(g_H1 + (size_t)dst*64))[lane];
    atomicAdd(&g_H2[(size_t)src*64 + 2*lane + 0], t * hv.x);
    atomicAdd(&g_H2[(size_t)src*64 + 2*lane + 1], t * hv.y);
}

// ---------------- launch ----------------
extern "C" void kernel_launch(void* const* d_in, const int* in_sizes, int n_in,
                              void* d_out, int out_size) {
    const float* score = (const float*)d_in[0];
    const float* H     = (const float*)d_in[1];
    const float* rel0  = (const float*)d_in[2];
    const float* rel1  = (const float*)d_in[3];
    const float* prior = (const float*)d_in[4];
    const float* qst   = (const float*)d_in[5];
    const float* qrl   = (const float*)d_in[6];
    const float* Wq    = (const float*)d_in[7];
    const float* Wk    = (const float*)d_in[8];
    const float* Wlin  = (const float*)d_in[9];
    const float* blin  = (const float*)d_in[10];
    const float* gamma = (const float*)d_in[11];
    const int*   e0    = (const int*)d_in[12];
    const int*   e1    = (const int*)d_in[13];
    float* out = (float*)d_out;

    float *pNT, *pZ, *pH1, *pH2, *pB1, *pB2, *pBL;
    cudaGetSymbolAddress((void**)&pNT, g_nodeT);
    cudaGetSymbolAddress((void**)&pZ,  g_Z);
    cudaGetSymbolAddress((void**)&pH1, g_H1);
    cudaGetSymbolAddress((void**)&pH2, g_H2);
    cudaGetSymbolAddress((void**)&pB1, g_B1);
    cudaGetSymbolAddress((void**)&pB2, g_B2);
    cudaGetSymbolAddress((void**)&pBL, g_BL);

    k_init1<<<(N_NODES + 255)/256, 256>>>(out);
    k_computeM<<<256, 256>>>(Wq, Wk);
    k_buildB<<<80, 256>>>(Wlin);
    k_qtab<<<NQ, 64>>>(qst, qrl);

    // ---- stage 1 ----
    k_gemm<<<dim3(N_NODES/64, 3), 256>>>(H, pB1, pNT, 192, 0, nullptr);
    k_gemm<<<dim3(E1N/64, 1), 256>>>(rel1, pB2, pZ, 64, 0, nullptr);
    k_logits<<<E1N/8, 256>>>(e1, rel1, H, prior, gamma, E1N);
    k_pass2<<<E1N/256, 256>>>(e1, 0, E1N);
    k_topk<<<NQ/8, 256>>>(e1, score, out);
    k_Hinit<<<(N_NODES*16 + 255)/256, 256>>>(H, pH1);
    k_scatter1<<<(NQ*KSEL)/8, 256>>>(H);

    // ---- stage 0 ----
    k_init2<<<(N_NODES + 255)/256, 256>>>();
    k_gemm<<<dim3(N_NODES/64, 3), 256>>>(pH1, pB1, pNT, 192, 0, nullptr);
    k_gemm<<<dim3(E0N/64, 1), 256>>>(rel0, pB2, pZ, 64, 0, nullptr);
    k_logits<<<E0N/8, 256>>>(e0, rel0, pH1, nullptr, gamma, E0N);
    k_pass2<<<E0N/256, 256>>>(e0, 1, E0N);
    k_Hinit<<<(N_NODES*16 + 255)/256, 256>>>(pH1, pH2);
    k_scatter0<<<E0N/8, 256>>>(e0);

    // ---- final linear + leaky relu ----
    k_gemm<<<dim3(N_NODES/64, 1), 256>>>(pH2, pBL, out + OFF_REPR, 64, 1, blin);
}

// round 2
// speedup vs baseline: 1.2145x; 1.2145x over previous
#include <cuda_runtime.h>
#include <cstdint>

#define N_NODES 200000
#define DIM 64
#define NQ 4096
#define GRP 64
#define E1N 262144
#define E0N 131072
#define KSEL 10

// Output layout (f32 concat): score[N], repr[N*64], pruned_edges[Q*K*8], orig_idx[Q*K]
#define OFF_REPR  (N_NODES)
#define OFF_PE    (N_NODES + N_NODES*DIM)
#define OFF_OI    (OFF_PE + NQ*KSEL*8)

// ---------------- scratch (device globals; no allocation) ----------------
__device__ float    g_M [256*256];
__device__ float    g_B1[64*192];       // [k][0:64]=M[k,0:64]->P, [64:128]=M[k,64:128]->U, [128:192]=M10^T->Wd
__device__ float    g_B2[64*64];        // M11^T   (B2[k][i] = M[64+i,64+k])
__device__ float    g_BL[64*64];        // W_lin^T
__device__ float    g_Bq[128*320];      // query-table weights: d|ce|v|T
__device__ float    g_QA[NQ*128];       // [qst|qrl]
__device__ float    g_QT[(size_t)NQ*320];
__device__ float    g_Qk0[NQ];
__device__ float    g_nodeT[(size_t)N_NODES*192];
__device__ float    g_quad[E1N];        // r^T M11 r per edge
__device__ float    g_logit[E1N];       // logits, then exp values (in place)
__device__ unsigned g_segmax[N_NODES];
__device__ float    g_segsum[N_NODES];
__device__ int      g_has[N_NODES];
__device__ float    g_H1[(size_t)N_NODES*DIM];
__device__ float    g_H2[(size_t)N_NODES*DIM];
__device__ int      g_psrc[NQ*KSEL];
__device__ int      g_pdst[NQ*KSEL];
__device__ float    g_ptrans[NQ*KSEL];
__device__ int      g_chg[NQ*KSEL];
__device__ int      g_ncnt;

// ---------------- helpers ----------------
__device__ __forceinline__ unsigned encf(float f) {
    unsigned u = __float_as_uint(f);
    return (u & 0x80000000u) ? ~u : (u | 0x80000000u);
}
__device__ __forceinline__ float decf(unsigned u) {
    return (u & 0x80000000u) ? __uint_as_float(u & 0x7fffffffu) : __uint_as_float(~u);
}

// ---------------- init kernels ----------------
__global__ void k_init1(float* outScore) {
    int i = blockIdx.x * blockDim.x + threadIdx.x;
    if (i < N_NODES) { g_segmax[i] = 0u; g_segsum[i] = 0.f; g_has[i] = 0; outScore[i] = 0.f; }
    if (i == 0) g_ncnt = 0;
}
__global__ void k_init2() {
    int i = blockIdx.x * blockDim.x + threadIdx.x;
    if (i < N_NODES) { g_segmax[i] = 0u; g_segsum[i] = 0.f; g_has[i] = 0; }
}

// M = Wq^T Wk
__global__ void k_computeM(const float* __restrict__ Wq, const float* __restrict__ Wk) {
    int i = blockIdx.x, j = threadIdx.x;
    float acc = 0.f;
    for (int k = 0; k < 256; k++) acc = fmaf(Wq[k*256 + i], Wk[k*256 + j], acc);
    g_M[i*256 + j] = acc;
}

__global__ void k_buildB(const float* __restrict__ W_lin) {
    int t = blockIdx.x * blockDim.x + threadIdx.x;
    if (t < 64*192) {
        int k = t / 192, c = t % 192;
        float v;
        if (c < 128) v = g_M[k*256 + c];                 // M00|M01
        else         v = g_M[(64 + (c-128))*256 + k];    // M10^T[k,i] = M[64+i, k]
        g_B1[t] = v;
    } else if (t < 64*192 + 64*64) {
        int t2 = t - 64*192; int k = t2 / 64, i = t2 % 64;
        g_B2[t2] = g_M[(64+i)*256 + (64+k)];             // M11^T
    } else if (t < 64*192 + 2*64*64) {
        int t3 = t - 64*192 - 64*64; int k = t3 / 64, i = t3 % 64;
        g_BL[t3] = W_lin[i*64 + k];                      // W_lin^T
    } else if (t < 64*192 + 2*64*64 + 128*320) {
        int t4 = t - 64*192 - 2*64*64;
        int k = t4 / 320, c = t4 % 320;
        float v;
        if      (c < 64)  v = g_M[(128+k)*256 + c];                              // d
        else if (c < 128) v = g_M[(128+k)*256 + c] + g_M[c*256 + 128 + k];       // ce
        else if (c < 192) v = g_M[(c-128)*256 + 128 + k];                        // v
        else              v = g_M[(c-64)*256 + 128 + k];                         // T (for k0)
        g_Bq[t4] = v;
    }
}

__global__ void k_packQA(const float* __restrict__ qst, const float* __restrict__ qrl) {
    int i = blockIdx.x * blockDim.x + threadIdx.x;   // over NQ*128
    int q = i >> 7, k = i & 127;
    g_QA[i] = (k < 64) ? qst[q*64 + k] : qrl[q*64 + k - 64];
}

// generic tiled GEMM: C[64x64 tile] = A[rows x 64] @ B[64 x ncols], strided.
// flags bit0: leaky-relu + bias epilogue; bit1: accumulate into C.
__global__ void k_gemm(const float* __restrict__ A, int lda,
                       const float* __restrict__ B, int ldb,
                       float* __restrict__ C, int ldc,
                       int flags, const float* __restrict__ bias) {
    __shared__ float sAT[64][72];
    __shared__ float sB[64][72];
    int t = threadIdx.x;
    int rb = blockIdx.x * 64, cb = blockIdx.y * 64;
    int r = t >> 4, c4 = (t & 15) * 4;
    for (int rr = r; rr < 64; rr += 16) {
        float4 av = *(const float4*)(A + (size_t)(rb + rr)*lda + c4);
        sAT[c4+0][rr] = av.x; sAT[c4+1][rr] = av.y; sAT[c4+2][rr] = av.z; sAT[c4+3][rr] = av.w;
    }
    for (int kk = r; kk < 64; kk += 16) {
        float4 bv = *(const float4*)(B + (size_t)kk*ldb + cb + c4);
        *(float4*)&sB[kk][c4] = bv;
    }
    __syncthreads();
    int tx = t & 15, ty = t >> 4;
    int r0 = ty * 4, c0 = tx * 4;
    float acc[4][4] = {};
    #pragma unroll
    for (int k = 0; k < 64; k++) {
        float4 av = *(const float4*)&sAT[k][r0];
        float4 bv = *(const float4*)&sB[k][c0];
        float a[4] = {av.x, av.y, av.z, av.w};
        float b[4] = {bv.x, bv.y, bv.z, bv.w};
        #pragma unroll
        for (int ii = 0; ii < 4; ii++)
            #pragma unroll
            for (int jj = 0; jj < 4; jj++)
                acc[ii][jj] = fmaf(a[ii], b[jj], acc[ii][jj]);
    }
    for (int ii = 0; ii < 4; ii++) {
        float* Cp = C + (size_t)(rb + r0 + ii)*ldc + cb + c0;
        float4 o = make_float4(acc[ii][0], acc[ii][1], acc[ii][2], acc[ii][3]);
        if (flags & 2) {
            float4 co = *(const float4*)Cp;
            o.x += co.x; o.y += co.y; o.z += co.z; o.w += co.w;
        }
        if (flags & 1) {
            o.x += bias[cb + c0 + 0]; o.y += bias[cb + c0 + 1];
            o.z += bias[cb + c0 + 2]; o.w += bias[cb + c0 + 3];
            o.x = o.x >= 0.f ? o.x : 0.01f * o.x;
            o.y = o.y >= 0.f ? o.y : 0.01f * o.y;
            o.z = o.z >= 0.f ? o.z : 0.01f * o.z;
            o.w = o.w >= 0.f ? o.w : 0.01f * o.w;
        }
        *(float4*)Cp = o;
    }
}

// quad[e] = rel[e] @ M11^T @ rel[e]  (Z GEMM fused with the row-dot; writes 1 float/edge)
__global__ void k_quad(const float* __restrict__ rel, float* __restrict__ quadOut) {
    __shared__ float sAT[64][72];
    __shared__ float sB[64][72];
    int t = threadIdx.x;
    int rb = blockIdx.x * 64;
    int r = t >> 4, c4 = (t & 15) * 4;
    for (int rr = r; rr < 64; rr += 16) {
        float4 av = *(const float4*)(rel + (size_t)(rb + rr)*64 + c4);
        sAT[c4+0][rr] = av.x; sAT[c4+1][rr] = av.y; sAT[c4+2][rr] = av.z; sAT[c4+3][rr] = av.w;
    }
    for (int kk = r; kk < 64; kk += 16) {
        *(float4*)&sB[kk][c4] = *(const float4*)(g_B2 + kk*64 + c4);
    }
    __syncthreads();
    int tx = t & 15, ty = t >> 4;
    int r0 = ty * 4, c0 = tx * 4;
    float acc[4][4] = {};
    #pragma unroll
    for (int k = 0; k < 64; k++) {
        float4 av = *(const float4*)&sAT[k][r0];
        float4 bv = *(const float4*)&sB[k][c0];
        float a[4] = {av.x, av.y, av.z, av.w};
        float b[4] = {bv.x, bv.y, bv.z, bv.w};
        #pragma unroll
        for (int ii = 0; ii < 4; ii++)
            #pragma unroll
            for (int jj = 0; jj < 4; jj++)
                acc[ii][jj] = fmaf(a[ii], b[jj], acc[ii][jj]);
    }
    // epilogue: row-dot Z tile against rel (re-read from global: L1-hot, coalesced)
    float qp[4];
    #pragma unroll
    for (int ii = 0; ii < 4; ii++) {
        float4 a = *(const float4*)(rel + (size_t)(rb + r0 + ii)*64 + c0);
        qp[ii] = acc[ii][0]*a.x + acc[ii][1]*a.y + acc[ii][2]*a.z + acc[ii][3]*a.w;
    }
    #pragma unroll
    for (int off = 8; off; off >>= 1)
        #pragma unroll
        for (int ii = 0; ii < 4; ii++)
            qp[ii] += __shfl_down_sync(~0u, qp[ii], off);
    if (tx == 0) {
        #pragma unroll
        for (int ii = 0; ii < 4; ii++) quadOut[rb + r0 + ii] = qp[ii];
    }
}

// k0[q] = QA[q] . QT[q][192:320]
__global__ void k_qk0() {
    int w = (blockIdx.x * blockDim.x + threadIdx.x) >> 5;
    int lane = threadIdx.x & 31;
    if (w >= NQ) return;
    float4 a = *(const float4*)(g_QA + (size_t)w*128 + lane*4);
    float4 b = *(const float4*)(g_QT + (size_t)w*320 + 192 + lane*4);
    float p = a.x*b.x + a.y*b.y + a.z*b.z + a.w*b.w;
    for (int o = 16; o; o >>= 1) p += __shfl_xor_sync(~0u, p, o);
    if (lane == 0) g_Qk0[w] = p;
}

// logits per edge (one warp/edge) + atomicMax into segment max
__global__ void k_logits(const int* __restrict__ edges, const float* __restrict__ rel,
                         const float* __restrict__ H, const float* __restrict__ prior,
                         const float* __restrict__ gammaPtr, int nE) {
    int w = (blockIdx.x * blockDim.x + threadIdx.x) >> 5;
    int lane = threadIdx.x & 31;
    if (w >= nE) return;
    int q = edges[w*8 + 0], src = edges[w*8 + 6], dst = edges[w*8 + 7];
    const float2* hs  = (const float2*)(H + (size_t)src*64);
    const float2* hd  = (const float2*)(H + (size_t)dst*64);
    const float2* nts = (const float2*)(g_nodeT + (size_t)src*192);
    const float2* ntd = (const float2*)(g_nodeT + (size_t)dst*192);
    const float2* rp  = (const float2*)(rel + (size_t)w*64);
    const float2* qd  = (const float2*)(g_QT + (size_t)q*320);
    const float2* qc  = (const float2*)(g_QT + (size_t)q*320 + 64);
    const float2* qv  = (const float2*)(g_QT + (size_t)q*320 + 128);
    float2 P  = nts[lane];
    float2 U  = nts[32 + lane];
    float2 Wd = ntd[64 + lane];
    float2 hdv = hd[lane], hsv = hs[lane], rv = rp[lane];
    float2 dq = qd[lane], cq = qc[lane], vq = qv[lane];
    float acc = (P.x + dq.x) * hdv.x + (P.y + dq.y) * hdv.y;
    acc = fmaf(rv.x, (U.x + cq.x + Wd.x), acc);
    acc = fmaf(rv.y, (U.y + cq.y + Wd.y), acc);
    acc = fmaf(vq.x, hsv.x, acc);
    acc = fmaf(vq.y, hsv.y, acc);
    for (int o = 16; o; o >>= 1) acc += __shfl_xor_sync(~0u, acc, o);
    if (lane == 0) {
        float l = acc + g_Qk0[q] + g_quad[w];
        if (prior) l = fmaf(gammaPtr[0], prior[w], l);
        g_logit[w] = l;
        atomicMax(&g_segmax[src], encf(l));
    }
}

// exp(l - max) + segment sum; optional "has src" marking (stage 0)
__global__ void k_pass2(const int* __restrict__ edges, int markHas, int nE) {
    int e = blockIdx.x * blockDim.x + threadIdx.x;
    if (e >= nE) return;
    int src = edges[e*8 + 6];
    float mx = decf(g_segmax[src]);
    float v = expf(g_logit[e] - mx);
    g_logit[e] = v;
    atomicAdd(&g_segsum[src], v);
    if (markHas) g_has[src] = 1;
}

// top-10 of 64 per query, write pruned outputs + node-score atomics + has flags
__global__ void k_topk(const int* __restrict__ edges1, const float* __restrict__ score,
                       float* __restrict__ out) {
    int w = (blockIdx.x * blockDim.x + threadIdx.x) >> 5;
    int lane = threadIdx.x & 31;
    if (w >= NQ) return;
    int g0 = lane, g1 = lane + 32;
    int e0 = w*64 + g0, e1 = w*64 + g1;
    int s0 = edges1[e0*8 + 6], s1 = edges1[e1*8 + 6];
    float tr0 = g_logit[e0] / g_segsum[s0];
    float tr1 = g_logit[e1] / g_segsum[s1];
    float v0 = tr0 * score[s0];
    float v1 = tr1 * score[s1];
    int myG = 0; float myTr = 0.f;
    for (int k = 0; k < KSEL; k++) {
        float bv; int bg; float bt;
        if (v0 >= v1) { bv = v0; bg = g0; bt = tr0; }
        else          { bv = v1; bg = g1; bt = tr1; }
        for (int o = 16; o; o >>= 1) {
            float ov = __shfl_xor_sync(~0u, bv, o);
            int   og = __shfl_xor_sync(~0u, bg, o);
            float ot = __shfl_xor_sync(~0u, bt, o);
            if (ov > bv || (ov == bv && og < bg)) { bv = ov; bg = og; bt = ot; }
        }
        if (lane == k) { myG = bg; myTr = bt; }
        if (g0 == bg) v0 = -__int_as_float(0x7f800000);
        if (g1 == bg) v1 = -__int_as_float(0x7f800000);
    }
    if (lane < KSEL) {
        int orig = w*64 + myG;
        int oi = w*KSEL + lane;
        int src = edges1[orig*8 + 6], dst = edges1[orig*8 + 7];
        g_psrc[oi] = src; g_pdst[oi] = dst; g_ptrans[oi] = myTr;
        g_has[src] = 1;
        atomicAdd(out + dst, myTr * score[src]);
        float* pe = out + OFF_PE + (size_t)oi*8;
        for (int c = 0; c < 8; c++) pe[c] = (float)edges1[orig*8 + c];
        out[OFF_OI + oi] = (float)orig;
    }
}

// Hdst[n] = has[n] ? 0 : Hsrc[n]; optionally build changed-node list
__global__ void k_Hinit(const float* __restrict__ Hsrc, float* __restrict__ Hdst, int buildList) {
    int i = blockIdx.x * blockDim.x + threadIdx.x;
    if (i >= N_NODES * 16) return;
    int n = i >> 4;
    int h = g_has[n];
    float4 v;
    if (h) v = make_float4(0.f, 0.f, 0.f, 0.f);
    else   v = ((const float4*)Hsrc)[i];
    ((float4*)Hdst)[i] = v;
    if (buildList && h && (i & 15) == 0) {
        int idx = atomicAdd(&g_ncnt, 1);
        g_chg[idx] = n;
    }
}

// delta nodeT update: nodeT[node] += (Hnew[node]-Hold[node]) @ B1, over changed list
__global__ void k_dgemm(const float* __restrict__ Hnew, const float* __restrict__ Hold) {
    int cnt = g_ncnt;
    int rb = blockIdx.x * 64;
    if (rb >= cnt) return;
    __shared__ float sAT[64][72];
    __shared__ float sB[64][72];
    __shared__ int snode[64];
    int t = threadIdx.x;
    int cb = blockIdx.y * 64;
    if (t < 64) snode[t] = (rb + t < cnt) ? g_chg[rb + t] : -1;
    __syncthreads();
    int r = t >> 4, c4 = (t & 15) * 4;
    for (int rr = r; rr < 64; rr += 16) {
        int node = snode[rr];
        float4 av = make_float4(0.f, 0.f, 0.f, 0.f);
        if (node >= 0) {
            float4 a = *(const float4*)(Hnew + (size_t)node*64 + c4);
            float4 b = *(const float4*)(Hold + (size_t)node*64 + c4);
            av = make_float4(a.x - b.x, a.y - b.y, a.z - b.z, a.w - b.w);
        }
        sAT[c4+0][rr] = av.x; sAT[c4+1][rr] = av.y; sAT[c4+2][rr] = av.z; sAT[c4+3][rr] = av.w;
    }
    for (int kk = r; kk < 64; kk += 16) {
        *(float4*)&sB[kk][c4] = *(const float4*)(g_B1 + kk*192 + cb + c4);
    }
    __syncthreads();
    int tx = t & 15, ty = t >> 4;
    int r0 = ty * 4, c0 = tx * 4;
    float acc[4][4] = {};
    #pragma unroll
    for (int k = 0; k < 64; k++) {
        float4 av = *(const float4*)&sAT[k][r0];
        float4 bv = *(const float4*)&sB[k][c0];
        float a[4] = {av.x, av.y, av.z, av.w};
        float b[4] = {bv.x, bv.y, bv.z, bv.w};
        #pragma unroll
        for (int ii = 0; ii < 4; ii++)
            #pragma unroll
            for (int jj = 0; jj < 4; jj++)
                acc[ii][jj] = fmaf(a[ii], b[jj], acc[ii][jj]);
    }
    #pragma unroll
    for (int ii = 0; ii < 4; ii++) {
        int node = snode[r0 + ii];
        if (node < 0) continue;
        float* Cp = g_nodeT + (size_t)node*192 + cb + c0;
        float4 co = *(const float4*)Cp;
        co.x += acc[ii][0]; co.y += acc[ii][1]; co.z += acc[ii][2]; co.w += acc[ii][3];
        *(float4*)Cp = co;
    }
}

// pruned-edge scatter: H1[src] += trans * H[dst]
__global__ void k_scatter1(const float* __restrict__ H) {
    int w = (blockIdx.x * blockDim.x + threadIdx.x) >> 5;
    int lane = threadIdx.x & 31;
    if (w >= NQ*KSEL) return;
    int src = g_psrc[w], dst = g_pdst[w];
    float t = g_ptrans[w];
    float2 hv = ((const float2*)(H + (size_t)dst*64))[lane];
    atomicAdd(&g_H1[(size_t)src*64 + 2*lane + 0], t * hv.x);
    atomicAdd(&g_H1[(size_t)src*64 + 2*lane + 1], t * hv.y);
}

// edges0 scatter: H2[src] += trans0 * H1[dst]
__global__ void k_scatter0(const int* __restrict__ edges0) {
    int w = (blockIdx.x * blockDim.x + threadIdx.x) >> 5;
    int lane = threadIdx.x & 31;
    if (w >= E0N) return;
    int src = edges0[w*8 + 6], dst = edges0[w*8 + 7];
    float t = g_logit[w] / g_segsum[src];
    float2 hv = ((const float2*)(g_H1 + (size_t)dst*64))[lane];
    atomicAdd(&g_H2[(size_t)src*64 + 2*lane + 0], t * hv.x);
    atomicAdd(&g_H2[(size_t)src*64 + 2*lane + 1], t * hv.y);
}

// ---------------- launch ----------------
extern "C" void kernel_launch(void* const* d_in, const int* in_sizes, int n_in,
                              void* d_out, int out_size) {
    const float* score = (const float*)d_in[0];
    const float* H     = (const float*)d_in[1];
    const float* rel0  = (const float*)d_in[2];
    const float* rel1  = (const float*)d_in[3];
    const float* prior = (const float*)d_in[4];
    const float* qst   = (const float*)d_in[5];
    const float* qrl   = (const float*)d_in[6];
    const float* Wq    = (const float*)d_in[7];
    const float* Wk    = (const float*)d_in[8];
    const float* Wlin  = (const float*)d_in[9];
    const float* blin  = (const float*)d_in[10];
    const float* gamma = (const float*)d_in[11];
    const int*   e0    = (const int*)d_in[12];
    const int*   e1    = (const int*)d_in[13];
    float* out = (float*)d_out;

    float *pNT, *pH1, *pH2, *pB1, *pBL, *pBq, *pQA, *pQT, *pQuad;
    cudaGetSymbolAddress((void**)&pNT, g_nodeT);
    cudaGetSymbolAddress((void**)&pH1, g_H1);
    cudaGetSymbolAddress((void**)&pH2, g_H2);
    cudaGetSymbolAddress((void**)&pB1, g_B1);
    cudaGetSymbolAddress((void**)&pBL, g_BL);
    cudaGetSymbolAddress((void**)&pBq, g_Bq);
    cudaGetSymbolAddress((void**)&pQA, g_QA);
    cudaGetSymbolAddress((void**)&pQT, g_QT);
    cudaGetSymbolAddress((void**)&pQuad, g_quad);

    k_init1<<<(N_NODES + 255)/256, 256>>>(out);
    k_computeM<<<256, 256>>>(Wq, Wk);
    k_buildB<<<(64*192 + 2*64*64 + 128*320 + 255)/256, 256>>>(Wlin);
    k_packQA<<<NQ*128/256, 256>>>(qst, qrl);

    // query tables via GEMM: QT = QA @ Bq (K=128 as two accumulating K=64 passes)
    k_gemm<<<dim3(NQ/64, 5), 256>>>(pQA,      128, pBq,          320, pQT, 320, 0, nullptr);
    k_gemm<<<dim3(NQ/64, 5), 256>>>(pQA + 64, 128, pBq + 64*320, 320, pQT, 320, 2, nullptr);
    k_qk0<<<NQ*32/256, 256>>>();

    // ---- stage 1 ----
    k_gemm<<<dim3(N_NODES/64, 3), 256>>>(H, 64, pB1, 192, pNT, 192, 0, nullptr);
    k_quad<<<E1N/64, 256>>>(rel1, pQuad);
    k_logits<<<E1N/8, 256>>>(e1, rel1, H, prior, gamma, E1N);
    k_pass2<<<E1N/256, 256>>>(e1, 0, E1N);
    k_topk<<<NQ/8, 256>>>(e1, score, out);
    k_Hinit<<<(N_NODES*16 + 255)/256, 256>>>(H, pH1, 1);
    k_scatter1<<<(NQ*KSEL)/8, 256>>>(H);

    // ---- stage 0 ----
    k_init2<<<(N_NODES + 255)/256, 256>>>();
    k_dgemm<<<dim3((NQ*KSEL)/64, 3), 256>>>(pH1, H);   // delta update of nodeT
    k_quad<<<E0N/64, 256>>>(rel0, pQuad);
    k_logits<<<E0N/8, 256>>>(e0, rel0, pH1, nullptr, gamma, E0N);
    k_pass2<<<E0N/256, 256>>>(e0, 1, E0N);
    k_Hinit<<<(N_NODES*16 + 255)/256, 256>>>(pH1, pH2, 0);
    k_scatter0<<<E0N/8, 256>>>(e0);

    // ---- final linear + leaky relu ----
    k_gemm<<<dim3(N_NODES/64, 1), 256>>>(pH2, 64, pBL, 64, out + OFF_REPR, 64, 1, blin);
}